// round 3
// baseline (speedup 1.0000x reference)
#include <cuda_runtime.h>
#include <cstdint>

// Problem shape (fixed by setup_inputs)
#define NPTS   8192
#define NFEAT  256
#define SPLITS 16
#define CHUNK  (NPTS / SPLITS)   // 512 refs -> 8KB smem as float4

// Per-split packed argmin partials: (ordered_d2_bits << 32) | ref_index.
// Every slot written by plain store each call -> no init, no atomics.
__device__ unsigned long long g_part[SPLITS * NPTS];

__device__ __forceinline__ unsigned int float_order(float f) {
    unsigned int u = __float_as_uint(f);
    return (u & 0x80000000u) ? ~u : (u | 0x80000000u);
}

// grid(NPTS/256, SPLITS), block(128). Each thread owns 2 queries (q, q+128),
// sharing one LDS.128 per reference across both -> ~6.5 instrs per (q,r) pair.
__global__ void __launch_bounds__(128) nn_argmin_kernel(
    const float* __restrict__ t1,   // refs  [3, NPTS]
    const float* __restrict__ t2)   // query [3, NPTS]
{
    __shared__ float4 refs[CHUNK];
    const int base = blockIdx.y * CHUNK;
    const int tid  = threadIdx.x;

    // Cooperative vectorized load: 128 threads x 4 refs = 512.
    {
        const int r4 = tid * 4;
        float4 x4 = *(const float4*)(t1 + base + r4);
        float4 y4 = *(const float4*)(t1 + NPTS + base + r4);
        float4 z4 = *(const float4*)(t1 + 2 * NPTS + base + r4);
        refs[r4 + 0] = make_float4(x4.x, y4.x, z4.x, fmaf(x4.x, x4.x, fmaf(y4.x, y4.x, z4.x * z4.x)));
        refs[r4 + 1] = make_float4(x4.y, y4.y, z4.y, fmaf(x4.y, x4.y, fmaf(y4.y, y4.y, z4.y * z4.y)));
        refs[r4 + 2] = make_float4(x4.z, y4.z, z4.z, fmaf(x4.z, x4.z, fmaf(y4.z, y4.z, z4.z * z4.z)));
        refs[r4 + 3] = make_float4(x4.w, y4.w, z4.w, fmaf(x4.w, x4.w, fmaf(y4.w, y4.w, z4.w * z4.w)));
    }
    __syncthreads();

    const int q0 = blockIdx.x * 256 + tid;   // this thread's two queries: q0, q0+128
    const float a0 = -2.0f * t2[q0],          a1 = -2.0f * t2[q0 + 128];
    const float b0 = -2.0f * t2[NPTS + q0],   b1 = -2.0f * t2[NPTS + q0 + 128];
    const float c0 = -2.0f * t2[2*NPTS + q0], c1 = -2.0f * t2[2*NPTS + q0 + 128];

    // 2 rotating partial minima per query break the compare dependency chain.
    float bv0[2] = {3.4e38f, 3.4e38f}, bv1[2] = {3.4e38f, 3.4e38f};
    int   bi0[2] = {0, 0},             bi1[2] = {0, 0};

    #pragma unroll 2
    for (int r = 0; r < CHUNK; r += 8) {
        #pragma unroll
        for (int u = 0; u < 8; ++u) {
            float4 f = refs[r + u];
            float base3 = fmaf(c0 * 0.0f, 0.0f, 0.0f); (void)base3;
            float v0 = fmaf(a0, f.x, fmaf(b0, f.y, fmaf(c0, f.z, f.w)));
            float v1 = fmaf(a1, f.x, fmaf(b1, f.y, fmaf(c1, f.z, f.w)));
            int p = u & 1;
            if (v0 < bv0[p]) { bv0[p] = v0; bi0[p] = r + u; }
            if (v1 < bv1[p]) { bv1[p] = v1; bi1[p] = r + u; }
        }
    }

    // Pack (ordered v, global idx); min == lex (v, idx) -> lowest index on tie,
    // matching jnp.argmin first-occurrence semantics.
    unsigned long long k0 = 0xFFFFFFFFFFFFFFFFull, k1 = 0xFFFFFFFFFFFFFFFFull;
    #pragma unroll
    for (int p = 0; p < 2; ++p) {
        unsigned long long t;
        t = ((unsigned long long)float_order(bv0[p]) << 32) | (unsigned int)(base + bi0[p]);
        k0 = (t < k0) ? t : k0;
        t = ((unsigned long long)float_order(bv1[p]) << 32) | (unsigned int)(base + bi1[p]);
        k1 = (t < k1) ? t : k1;
    }
    g_part[blockIdx.y * NPTS + q0]       = k0;
    g_part[blockIdx.y * NPTS + q0 + 128] = k1;
}

// grid(NPTS/256, 512/32) = (32, 16), block(256). Block covers 32 rows x 256
// queries. y<8: gather emb1 rows (combine split partials in smem first);
// y>=8: straight float4 copy of emb2. Each thread: 8 independent float4 stores.
__global__ void __launch_bounds__(256) gather_concat_kernel(
    const float* __restrict__ emb1,
    const float* __restrict__ emb2,
    float* __restrict__ out)
{
    const int tid = threadIdx.x;
    const int j0  = blockIdx.x * 256;
    const int qg  = (tid & 63) * 4;        // float4 group within j-tile
    const int rb  = (tid >> 6) * 8;        // 8-row group within f-tile

    if (blockIdx.y < 8) {
        __shared__ int inds[256];
        // Combine SPLITS partials for one query per thread.
        unsigned long long m = g_part[j0 + tid];
        #pragma unroll
        for (int s = 1; s < SPLITS; ++s) {
            unsigned long long v = g_part[s * NPTS + j0 + tid];
            m = (v < m) ? v : m;
        }
        inds[tid] = (int)(unsigned int)(m & 0xFFFFFFFFull);
        __syncthreads();

        const int i0 = inds[qg], i1 = inds[qg+1], i2 = inds[qg+2], i3 = inds[qg+3];
        const int f0 = blockIdx.y * 32 + rb;
        #pragma unroll
        for (int r = 0; r < 8; ++r) {
            const float* row = emb1 + (size_t)(f0 + r) * NPTS;
            float4 v = make_float4(row[i0], row[i1], row[i2], row[i3]);
            *(float4*)(out + (size_t)(f0 + r) * NPTS + j0 + qg) = v;
        }
    } else {
        const int fsrc = (blockIdx.y - 8) * 32 + rb;   // emb2 row
        #pragma unroll
        for (int r = 0; r < 8; ++r) {
            float4 v = *(const float4*)(emb2 + (size_t)(fsrc + r) * NPTS + j0 + qg);
            *(float4*)(out + (size_t)(NFEAT + fsrc + r) * NPTS + j0 + qg) = v;
        }
    }
}

extern "C" void kernel_launch(void* const* d_in, const int* in_sizes, int n_in,
                              void* d_out, int out_size) {
    const float* emb1 = (const float*)d_in[0];
    const float* emb2 = (const float*)d_in[1];
    const float* t1   = (const float*)d_in[2];
    const float* t2   = (const float*)d_in[3];
    float* out = (float*)d_out;

    dim3 nn_grid(NPTS / 256, SPLITS);
    nn_argmin_kernel<<<nn_grid, 128>>>(t1, t2);

    dim3 g_grid(NPTS / 256, 16);
    gather_concat_kernel<<<g_grid, 256>>>(emb1, emb2, out);
}

// round 4
// speedup vs baseline: 1.3744x; 1.3744x over previous
#include <cuda_runtime.h>
#include <cstdint>

#define NPTS   8192
#define NFEAT  256
#define SPLITS 32
#define CHUNK  (NPTS / SPLITS)   // 256 refs -> 4KB smem as float4

// Per-split packed argmin partials: (ordered_d2_bits << 32) | ref_index.
__device__ unsigned long long g_part[SPLITS * NPTS];
// Final combined indices.
__device__ int g_inds[NPTS];

__device__ __forceinline__ unsigned int float_order(float f) {
    unsigned int u = __float_as_uint(f);
    return (u & 0x80000000u) ? ~u : (u | 0x80000000u);
}

// grid(NPTS/256, SPLITS), block(128). Each thread owns 2 queries (q, q+128);
// one smem ref read feeds both. argmin_i (|r_i|^2 - 2 q.r_i) == argmin d2.
__global__ void __launch_bounds__(128) nn_argmin_kernel(
    const float* __restrict__ t1,   // refs  [3, NPTS]
    const float* __restrict__ t2)   // query [3, NPTS]
{
    __shared__ float4 refs[CHUNK];
    const int base = blockIdx.y * CHUNK;
    const int tid  = threadIdx.x;

    // Cooperative load: 128 threads x 2 refs.
    {
        const int r2 = tid * 2;
        float2 x2 = *(const float2*)(t1 + base + r2);
        float2 y2 = *(const float2*)(t1 + NPTS + base + r2);
        float2 z2 = *(const float2*)(t1 + 2 * NPTS + base + r2);
        refs[r2 + 0] = make_float4(x2.x, y2.x, z2.x, fmaf(x2.x, x2.x, fmaf(y2.x, y2.x, z2.x * z2.x)));
        refs[r2 + 1] = make_float4(x2.y, y2.y, z2.y, fmaf(x2.y, x2.y, fmaf(y2.y, y2.y, z2.y * z2.y)));
    }
    __syncthreads();

    const int q0 = blockIdx.x * 256 + tid;
    const float a0 = -2.0f * t2[q0],          a1 = -2.0f * t2[q0 + 128];
    const float b0 = -2.0f * t2[NPTS + q0],   b1 = -2.0f * t2[NPTS + q0 + 128];
    const float c0 = -2.0f * t2[2*NPTS + q0], c1 = -2.0f * t2[2*NPTS + q0 + 128];

    // 2 rotating slots per query; FSEL-form updates (pred-as-data, 4cyc).
    float bv0[2] = {3.4e38f, 3.4e38f}, bv1[2] = {3.4e38f, 3.4e38f};
    int   bi0[2] = {0, 0},             bi1[2] = {0, 0};

    #pragma unroll
    for (int r = 0; r < CHUNK; r += 8) {
        #pragma unroll
        for (int u = 0; u < 8; ++u) {
            float4 f = refs[r + u];
            float v0 = fmaf(a0, f.x, fmaf(b0, f.y, fmaf(c0, f.z, f.w)));
            float v1 = fmaf(a1, f.x, fmaf(b1, f.y, fmaf(c1, f.z, f.w)));
            const int p = u & 1;
            const int idx = r + u;
            bool l0 = v0 < bv0[p];
            bv0[p] = l0 ? v0 : bv0[p];
            bi0[p] = l0 ? idx : bi0[p];
            bool l1 = v1 < bv1[p];
            bv1[p] = l1 ? v1 : bv1[p];
            bi1[p] = l1 ? idx : bi1[p];
        }
    }

    // Lex-min on (ordered v, global idx): lowest index on ties, matching
    // jnp.argmin first-occurrence semantics.
    unsigned long long k0 = 0xFFFFFFFFFFFFFFFFull, k1 = 0xFFFFFFFFFFFFFFFFull;
    #pragma unroll
    for (int p = 0; p < 2; ++p) {
        unsigned long long t;
        t = ((unsigned long long)float_order(bv0[p]) << 32) | (unsigned int)(base + bi0[p]);
        k0 = (t < k0) ? t : k0;
        t = ((unsigned long long)float_order(bv1[p]) << 32) | (unsigned int)(base + bi1[p]);
        k1 = (t < k1) ? t : k1;
    }
    g_part[blockIdx.y * NPTS + q0]       = k0;
    g_part[blockIdx.y * NPTS + q0 + 128] = k1;
}

// grid(NPTS/256), block(256): min-combine SPLITS partials -> g_inds.
__global__ void __launch_bounds__(256) combine_kernel() {
    const int q = blockIdx.x * 256 + threadIdx.x;
    unsigned long long m = g_part[q];
    #pragma unroll
    for (int s = 1; s < SPLITS; ++s) {
        unsigned long long v = g_part[s * NPTS + q];
        m = (v < m) ? v : m;
    }
    g_inds[q] = (int)(unsigned int)(m & 0xFFFFFFFFull);
}

// grid(256 + 128), block(256).
// Blocks [0,256): feature row f=b. Load emb1 row into smem (coalesced),
//   gather via LDS (random banks ~3-4x conflict, no L1 wavefront explosion),
//   store float4 coalesced.
// Blocks [256,384): stream-copy emb2 -> out upper half (float4).
__global__ void __launch_bounds__(256) gather_concat_kernel(
    const float* __restrict__ emb1,
    const float* __restrict__ emb2,
    float* __restrict__ out)
{
    const int tid = threadIdx.x;
    const int b   = blockIdx.x;

    if (b < NFEAT) {
        __shared__ float srow[NPTS];
        const float4* rowsrc = (const float4*)(emb1 + (size_t)b * NPTS);
        float4* srow4 = (float4*)srow;
        #pragma unroll
        for (int i = 0; i < NPTS / 4 / 256; ++i)      // 8 float4 per thread
            srow4[i * 256 + tid] = rowsrc[i * 256 + tid];
        __syncthreads();

        float* dst = out + (size_t)b * NPTS;
        #pragma unroll
        for (int k = 0; k < 8; ++k) {
            const int j = tid * 4 + k * 1024;
            int4 iv = *(const int4*)(g_inds + j);
            float4 v = make_float4(srow[iv.x], srow[iv.y], srow[iv.z], srow[iv.w]);
            *(float4*)(dst + j) = v;
        }
    } else {
        const int c = b - NFEAT;                       // 0..127
        const float4* src = (const float4*)emb2;
        float4* dst = (float4*)(out + (size_t)NFEAT * NPTS);
        #pragma unroll
        for (int i = 0; i < 16; ++i) {                 // 128 blocks x 4096 f4
            const int o = c * 4096 + i * 256 + tid;
            dst[o] = src[o];
        }
    }
}

extern "C" void kernel_launch(void* const* d_in, const int* in_sizes, int n_in,
                              void* d_out, int out_size) {
    const float* emb1 = (const float*)d_in[0];
    const float* emb2 = (const float*)d_in[1];
    const float* t1   = (const float*)d_in[2];
    const float* t2   = (const float*)d_in[3];
    float* out = (float*)d_out;

    dim3 nn_grid(NPTS / 256, SPLITS);
    nn_argmin_kernel<<<nn_grid, 128>>>(t1, t2);

    combine_kernel<<<NPTS / 256, 256>>>();

    gather_concat_kernel<<<NFEAT + 128, 256>>>(emb1, emb2, out);
}

// round 5
// speedup vs baseline: 1.3772x; 1.0021x over previous
#include <cuda_runtime.h>
#include <cstdint>

#define NPTS   8192
#define NFEAT  256
#define SPLITS 32
#define CHUNK  (NPTS / SPLITS)   // 256 refs -> 4KB smem (pair-interleaved)

// Per-split packed argmin partials: (ordered_d2_bits << 32) | ref_index.
__device__ unsigned long long g_part[SPLITS * NPTS];
__device__ int g_inds[NPTS];

__device__ __forceinline__ unsigned int float_order(float f) {
    unsigned int u = __float_as_uint(f);
    return (u & 0x80000000u) ? ~u : (u | 0x80000000u);
}

// ---- packed f32x2 helpers (FFMA2 is PTX-only; ptxas won't auto-fuse) ----
__device__ __forceinline__ uint64_t bcast2(float f) {
    uint64_t r; asm("mov.b64 %0, {%1, %1};" : "=l"(r) : "f"(f)); return r;
}
__device__ __forceinline__ uint64_t fma2(uint64_t a, uint64_t b, uint64_t c) {
    uint64_t d; asm("fma.rn.f32x2 %0, %1, %2, %3;" : "=l"(d) : "l"(a), "l"(b), "l"(c));
    return d;
}
__device__ __forceinline__ void unpack2(uint64_t v, float& lo, float& hi) {
    asm("mov.b64 {%0, %1}, %2;" : "=f"(lo), "=f"(hi) : "l"(v));
}
__device__ __forceinline__ void lds_v2u64(uint32_t addr, uint64_t& a, uint64_t& b) {
    asm volatile("ld.shared.v2.u64 {%0, %1}, [%2];" : "=l"(a), "=l"(b) : "r"(addr));
}

// grid(NPTS/256, SPLITS), block(128). Each thread owns queries q0, q0+128.
// smem holds CHUNK refs pair-interleaved: pair i -> {x0,x1,y0,y1},{z0,z1,w0,w1}.
// v = fma(a,x, fma(b,y, fma(c,z, w))) -- same association as prior rounds, so
// all argmin decisions are bit-identical to the passing kernel.
__global__ void __launch_bounds__(128) nn_argmin_kernel(
    const float* __restrict__ t1,   // refs  [3, NPTS]
    const float* __restrict__ t2)   // query [3, NPTS]
{
    __shared__ float4 refs[CHUNK / 2 * 2];   // 256 float4 = 4KB
    const int base = blockIdx.y * CHUNK;
    const int tid  = threadIdx.x;

    // Prologue: thread tid packs ref pair (2tid, 2tid+1).
    {
        const int r2 = tid * 2;
        float2 x2 = *(const float2*)(t1 + base + r2);
        float2 y2 = *(const float2*)(t1 + NPTS + base + r2);
        float2 z2 = *(const float2*)(t1 + 2 * NPTS + base + r2);
        float w0 = fmaf(x2.x, x2.x, fmaf(y2.x, y2.x, z2.x * z2.x));
        float w1 = fmaf(x2.y, x2.y, fmaf(y2.y, y2.y, z2.y * z2.y));
        refs[2 * tid]     = make_float4(x2.x, x2.y, y2.x, y2.y);
        refs[2 * tid + 1] = make_float4(z2.x, z2.y, w0, w1);
    }
    __syncthreads();

    const int q0 = blockIdx.x * 256 + tid;
    const uint64_t aa0 = bcast2(-2.0f * t2[q0]);
    const uint64_t bb0 = bcast2(-2.0f * t2[NPTS + q0]);
    const uint64_t cc0 = bcast2(-2.0f * t2[2 * NPTS + q0]);
    const uint64_t aa1 = bcast2(-2.0f * t2[q0 + 128]);
    const uint64_t bb1 = bcast2(-2.0f * t2[NPTS + q0 + 128]);
    const uint64_t cc1 = bcast2(-2.0f * t2[2 * NPTS + q0 + 128]);

    // Per query: slot E (even refs) and slot O (odd refs).
    float bv0e = 3.4e38f, bv0o = 3.4e38f, bv1e = 3.4e38f, bv1o = 3.4e38f;
    int   bi0e = 0, bi0o = 1, bi1e = 0, bi1o = 1;

    const uint32_t sbase = (uint32_t)__cvta_generic_to_shared(refs);

    #pragma unroll 4
    for (int i = 0; i < CHUNK / 2; ++i) {
        uint64_t x01, y01, z01, w01;
        lds_v2u64(sbase + i * 32,      x01, y01);
        lds_v2u64(sbase + i * 32 + 16, z01, w01);

        uint64_t v0p = fma2(aa0, x01, fma2(bb0, y01, fma2(cc0, z01, w01)));
        uint64_t v1p = fma2(aa1, x01, fma2(bb1, y01, fma2(cc1, z01, w01)));

        float v0e, v0o, v1e, v1o;
        unpack2(v0p, v0e, v0o);
        unpack2(v1p, v1e, v1o);

        const int ie = 2 * i, io = 2 * i + 1;
        if (v0e < bv0e) { bv0e = v0e; bi0e = ie; }
        if (v0o < bv0o) { bv0o = v0o; bi0o = io; }
        if (v1e < bv1e) { bv1e = v1e; bi1e = ie; }
        if (v1o < bv1o) { bv1o = v1o; bi1o = io; }
    }

    // Lex-min on (ordered v, global idx): lowest index wins ties, matching
    // jnp.argmin first-occurrence semantics.
    unsigned long long k0, k1, t;
    k0 = ((unsigned long long)float_order(bv0e) << 32) | (unsigned int)(base + bi0e);
    t  = ((unsigned long long)float_order(bv0o) << 32) | (unsigned int)(base + bi0o);
    k0 = (t < k0) ? t : k0;
    k1 = ((unsigned long long)float_order(bv1e) << 32) | (unsigned int)(base + bi1e);
    t  = ((unsigned long long)float_order(bv1o) << 32) | (unsigned int)(base + bi1o);
    k1 = (t < k1) ? t : k1;

    g_part[blockIdx.y * NPTS + q0]       = k0;
    g_part[blockIdx.y * NPTS + q0 + 128] = k1;
}

// grid(NPTS/256), block(256): min-combine SPLITS partials -> g_inds.
__global__ void __launch_bounds__(256) combine_kernel() {
    const int q = blockIdx.x * 256 + threadIdx.x;
    unsigned long long m = g_part[q];
    #pragma unroll
    for (int s = 1; s < SPLITS; ++s) {
        unsigned long long v = g_part[s * NPTS + q];
        m = (v < m) ? v : m;
    }
    g_inds[q] = (int)(unsigned int)(m & 0xFFFFFFFFull);
}

// grid(256 + 128), block(256).
// Blocks [0,256): feature row f=b: emb1 row -> smem (coalesced), gather via
//   LDS (no L1 wavefront amplification), float4 coalesced stores.
// Blocks [256,384): stream-copy emb2 -> out upper half (float4).
__global__ void __launch_bounds__(256) gather_concat_kernel(
    const float* __restrict__ emb1,
    const float* __restrict__ emb2,
    float* __restrict__ out)
{
    const int tid = threadIdx.x;
    const int b   = blockIdx.x;

    if (b < NFEAT) {
        __shared__ float srow[NPTS];
        const float4* rowsrc = (const float4*)(emb1 + (size_t)b * NPTS);
        float4* srow4 = (float4*)srow;
        #pragma unroll
        for (int i = 0; i < NPTS / 4 / 256; ++i)
            srow4[i * 256 + tid] = rowsrc[i * 256 + tid];
        __syncthreads();

        float* dst = out + (size_t)b * NPTS;
        #pragma unroll
        for (int k = 0; k < 8; ++k) {
            const int j = tid * 4 + k * 1024;
            int4 iv = *(const int4*)(g_inds + j);
            float4 v = make_float4(srow[iv.x], srow[iv.y], srow[iv.z], srow[iv.w]);
            *(float4*)(dst + j) = v;
        }
    } else {
        const int c = b - NFEAT;
        const float4* src = (const float4*)emb2;
        float4* dst = (float4*)(out + (size_t)NFEAT * NPTS);
        #pragma unroll
        for (int i = 0; i < 16; ++i) {
            const int o = c * 4096 + i * 256 + tid;
            dst[o] = src[o];
        }
    }
}

extern "C" void kernel_launch(void* const* d_in, const int* in_sizes, int n_in,
                              void* d_out, int out_size) {
    const float* emb1 = (const float*)d_in[0];
    const float* emb2 = (const float*)d_in[1];
    const float* t1   = (const float*)d_in[2];
    const float* t2   = (const float*)d_in[3];
    float* out = (float*)d_out;

    dim3 nn_grid(NPTS / 256, SPLITS);
    nn_argmin_kernel<<<nn_grid, 128>>>(t1, t2);

    combine_kernel<<<NPTS / 256, 256>>>();

    gather_concat_kernel<<<NFEAT + 128, 256>>>(emb1, emb2, out);
}

// round 7
// speedup vs baseline: 1.5746x; 1.1434x over previous
#include <cuda_runtime.h>
#include <cstdint>

#define NPTS   8192
#define NFEAT  256
#define SPLITS 64
#define CHUNK  (NPTS / SPLITS)      // 128 refs -> 2KB smem (pair-interleaved)
#define NN_BLOCKS   (NPTS / 256 * SPLITS)   // 2048
#define COPY_BLOCKS 128

// Per-split packed argmin partials: (ordered_d2_bits << 32) | ref_index.
__device__ unsigned long long g_part[SPLITS * NPTS];
__device__ int g_inds[NPTS];

__device__ __forceinline__ unsigned int float_order(float f) {
    unsigned int u = __float_as_uint(f);
    return (u & 0x80000000u) ? ~u : (u | 0x80000000u);
}

// ---- packed f32x2 helpers (FFMA2 is PTX-only) ----
__device__ __forceinline__ uint64_t bcast2(float f) {
    uint64_t r; asm("mov.b64 %0, {%1, %1};" : "=l"(r) : "f"(f)); return r;
}
__device__ __forceinline__ uint64_t fma2(uint64_t a, uint64_t b, uint64_t c) {
    uint64_t d; asm("fma.rn.f32x2 %0, %1, %2, %3;" : "=l"(d) : "l"(a), "l"(b), "l"(c));
    return d;
}
__device__ __forceinline__ void unpack2(uint64_t v, float& lo, float& hi) {
    asm("mov.b64 {%0, %1}, %2;" : "=f"(lo), "=f"(hi) : "l"(v));
}
__device__ __forceinline__ void lds_v2u64(uint32_t addr, uint64_t& a, uint64_t& b) {
    asm volatile("ld.shared.v2.u64 {%0, %1}, [%2];" : "=l"(a), "=l"(b) : "r"(addr));
}

// grid(NN_BLOCKS + COPY_BLOCKS), block(128).
// Blocks [0, NN_BLOCKS): argmin. qtile = b & 31, split = b >> 5.
// Blocks [NN_BLOCKS, +COPY_BLOCKS): stream-copy emb2 -> out upper half
//   (128 blocks x 32 iters x 128 thr = 524288 float4 — full 8.4MB).
__global__ void __launch_bounds__(128) nn_argmin_kernel(
    const float* __restrict__ t1,   // refs  [3, NPTS]
    const float* __restrict__ t2,   // query [3, NPTS]
    const float* __restrict__ emb2,
    float* __restrict__ out)
{
    const int tid = threadIdx.x;

    if (blockIdx.x >= NN_BLOCKS) {
        const int c = blockIdx.x - NN_BLOCKS;
        const float4* src = (const float4*)emb2;
        float4* dst = (float4*)(out + (size_t)NFEAT * NPTS);
        #pragma unroll
        for (int i = 0; i < 32; ++i) {
            const int o = c * 4096 + i * 128 + tid;
            dst[o] = src[o];
        }
        return;
    }

    __shared__ float4 refs[CHUNK];          // 128 float4 = 2KB
    const int split = blockIdx.x >> 5;
    const int qtile = blockIdx.x & 31;
    const int base  = split * CHUNK;

    // Prologue: threads 0..63 each pack one ref pair:
    // pair i -> {x0,x1,y0,y1},{z0,z1,w0,w1}.
    if (tid < CHUNK / 2) {
        const int r2 = tid * 2;
        float2 x2 = *(const float2*)(t1 + base + r2);
        float2 y2 = *(const float2*)(t1 + NPTS + base + r2);
        float2 z2 = *(const float2*)(t1 + 2 * NPTS + base + r2);
        float w0 = fmaf(x2.x, x2.x, fmaf(y2.x, y2.x, z2.x * z2.x));
        float w1 = fmaf(x2.y, x2.y, fmaf(y2.y, y2.y, z2.y * z2.y));
        refs[2 * tid]     = make_float4(x2.x, x2.y, y2.x, y2.y);
        refs[2 * tid + 1] = make_float4(z2.x, z2.y, w0, w1);
    }
    __syncthreads();

    const int q0 = qtile * 256 + tid;
    const uint64_t aa0 = bcast2(-2.0f * t2[q0]);
    const uint64_t bb0 = bcast2(-2.0f * t2[NPTS + q0]);
    const uint64_t cc0 = bcast2(-2.0f * t2[2 * NPTS + q0]);
    const uint64_t aa1 = bcast2(-2.0f * t2[q0 + 128]);
    const uint64_t bb1 = bcast2(-2.0f * t2[NPTS + q0 + 128]);
    const uint64_t cc1 = bcast2(-2.0f * t2[2 * NPTS + q0 + 128]);

    float bv0e = 3.4e38f, bv0o = 3.4e38f, bv1e = 3.4e38f, bv1o = 3.4e38f;
    int   bi0e = 0, bi0o = 1, bi1e = 0, bi1o = 1;

    const uint32_t sbase = (uint32_t)__cvta_generic_to_shared(refs);

    // v = fma(a,x, fma(b,y, fma(c,z, w))) — same association as the passing
    // kernels, so all argmin decisions are bit-identical.
    #pragma unroll 8
    for (int i = 0; i < CHUNK / 2; ++i) {
        uint64_t x01, y01, z01, w01;
        lds_v2u64(sbase + i * 32,      x01, y01);
        lds_v2u64(sbase + i * 32 + 16, z01, w01);

        uint64_t v0p = fma2(aa0, x01, fma2(bb0, y01, fma2(cc0, z01, w01)));
        uint64_t v1p = fma2(aa1, x01, fma2(bb1, y01, fma2(cc1, z01, w01)));

        float v0e, v0o, v1e, v1o;
        unpack2(v0p, v0e, v0o);
        unpack2(v1p, v1e, v1o);

        const int ie = 2 * i, io = 2 * i + 1;
        if (v0e < bv0e) { bv0e = v0e; bi0e = ie; }
        if (v0o < bv0o) { bv0o = v0o; bi0o = io; }
        if (v1e < bv1e) { bv1e = v1e; bi1e = ie; }
        if (v1o < bv1o) { bv1o = v1o; bi1o = io; }
    }

    // Lex-min on (ordered v, global idx): lowest index wins ties, matching
    // jnp.argmin first-occurrence semantics.
    unsigned long long k0, k1, t;
    k0 = ((unsigned long long)float_order(bv0e) << 32) | (unsigned int)(base + bi0e);
    t  = ((unsigned long long)float_order(bv0o) << 32) | (unsigned int)(base + bi0o);
    k0 = (t < k0) ? t : k0;
    k1 = ((unsigned long long)float_order(bv1e) << 32) | (unsigned int)(base + bi1e);
    t  = ((unsigned long long)float_order(bv1o) << 32) | (unsigned int)(base + bi1o);
    k1 = (t < k1) ? t : k1;

    g_part[split * NPTS + q0]       = k0;
    g_part[split * NPTS + q0 + 128] = k1;
}

// grid(NPTS/256), block(256): min-combine SPLITS partials -> g_inds.
__global__ void __launch_bounds__(256) combine_kernel() {
    const int q = blockIdx.x * 256 + threadIdx.x;
    unsigned long long m = g_part[q];
    #pragma unroll
    for (int s = 1; s < SPLITS; ++s) {
        unsigned long long v = g_part[s * NPTS + q];
        m = (v < m) ? v : m;
    }
    g_inds[q] = (int)(unsigned int)(m & 0xFFFFFFFFull);
}

// grid(NFEAT), block(256). Block b: emb1 row b -> smem (coalesced), gather
// via LDS (no L1 wavefront amplification), float4 coalesced stores.
__global__ void __launch_bounds__(256) gather_kernel(
    const float* __restrict__ emb1,
    float* __restrict__ out)
{
    const int tid = threadIdx.x;
    const int b   = blockIdx.x;

    __shared__ float srow[NPTS];
    const float4* rowsrc = (const float4*)(emb1 + (size_t)b * NPTS);
    float4* srow4 = (float4*)srow;
    #pragma unroll
    for (int i = 0; i < NPTS / 4 / 256; ++i)
        srow4[i * 256 + tid] = rowsrc[i * 256 + tid];
    __syncthreads();

    float* dst = out + (size_t)b * NPTS;
    #pragma unroll
    for (int k = 0; k < 8; ++k) {
        const int j = tid * 4 + k * 1024;
        int4 iv = *(const int4*)(g_inds + j);
        float4 v = make_float4(srow[iv.x], srow[iv.y], srow[iv.z], srow[iv.w]);
        *(float4*)(dst + j) = v;
    }
}

extern "C" void kernel_launch(void* const* d_in, const int* in_sizes, int n_in,
                              void* d_out, int out_size) {
    const float* emb1 = (const float*)d_in[0];
    const float* emb2 = (const float*)d_in[1];
    const float* t1   = (const float*)d_in[2];
    const float* t2   = (const float*)d_in[3];
    float* out = (float*)d_out;

    nn_argmin_kernel<<<NN_BLOCKS + COPY_BLOCKS, 128>>>(t1, t2, emb2, out);
    combine_kernel<<<NPTS / 256, 256>>>();
    gather_kernel<<<NFEAT, 256>>>(emb1, out);
}